// round 1
// baseline (speedup 1.0000x reference)
#include <cuda_runtime.h>

// Problem constants (fixed by the reference)
#define BN   4096
#define LEN  60
#define TS   60
#define HD   256
#define ID   6
#define OD   6
#define GD   1024      // 4*H
#define ROWS 16        // batch rows per CTA
#define NTH  256
#define KD   264       // decoder input K (262) padded to 264 for 16B alignment
#define NCTA (BN / ROWS)

typedef unsigned long long u64;

// ---------------- device scratch (allocation-free: static __device__ globals) ----------------
__device__ float g_WihT_e[ID * GD];
__device__ float g_WhhT_e[HD * GD];
__device__ float g_be[GD];
__device__ float g_WihT_d[KD * GD];   // rows 262..263 zero
__device__ float g_WhhT_d[HD * GD];
__device__ float g_bd[GD];
__device__ float g_l1T[HD * HD];
__device__ float g_l2T[HD * OD];
__device__ float g_attnW[LEN * KD];   // padded row stride 264
__device__ float g_enc[(size_t)BN * LEN * HD];   // encoder outputs [B][L][H]

// ---------------- packed fp32x2 helpers (FFMA2: 2x fp32 throughput on sm_103a) ----------------
__device__ __forceinline__ u64 pack2(float v) {
    u64 r; asm("mov.b64 %0, {%1, %1};" : "=l"(r) : "f"(v)); return r;
}
__device__ __forceinline__ u64 fma2(u64 a, u64 b, u64 c) {
    u64 d; asm("fma.rn.f32x2 %0, %1, %2, %3;" : "=l"(d) : "l"(a), "l"(b), "l"(c)); return d;
}
__device__ __forceinline__ float2 unpk(u64 v) {
    float2 f; asm("mov.b64 {%0, %1}, %2;" : "=f"(f.x), "=f"(f.y) : "l"(v)); return f;
}
__device__ __forceinline__ float sigmf(float x) { return 1.0f / (1.0f + __expf(-x)); }

// Accumulate acc[4 rows][8 u64 (=16 cols)] += A_smem[row][k] * W[k][j0..j0+16) over k in [0,K)
// A rows broadcast from smem (all lanes in a warp share rg -> broadcast), W streamed LDG.128.
__device__ __forceinline__ void gemm_part(u64 acc[4][8],
                                          const float* __restrict__ Asm, int lda, int K,
                                          const float* __restrict__ W, int rg, int j0) {
    for (int k = 0; k < K; k += 4) {
        float4 av[4];
#pragma unroll
        for (int i = 0; i < 4; i++)
            av[i] = *(const float4*)&Asm[(rg * 4 + i) * lda + k];
#pragma unroll
        for (int kk = 0; kk < 4; kk++) {
            const ulonglong2* wp = (const ulonglong2*)&W[(k + kk) * GD + j0];
            ulonglong2 w0 = wp[0], w1 = wp[1], w2 = wp[2], w3 = wp[3];
#pragma unroll
            for (int i = 0; i < 4; i++) {
                u64 ab = pack2(((const float*)&av[i])[kk]);
                acc[i][0] = fma2(ab, w0.x, acc[i][0]);
                acc[i][1] = fma2(ab, w0.y, acc[i][1]);
                acc[i][2] = fma2(ab, w1.x, acc[i][2]);
                acc[i][3] = fma2(ab, w1.y, acc[i][3]);
                acc[i][4] = fma2(ab, w2.x, acc[i][4]);
                acc[i][5] = fma2(ab, w2.y, acc[i][5]);
                acc[i][6] = fma2(ab, w3.x, acc[i][6]);
                acc[i][7] = fma2(ab, w3.y, acc[i][7]);
            }
        }
    }
}

// ---------------- prep: transpose weights, fold biases, pad ----------------
__global__ void prep_kernel(const float* __restrict__ eWih, const float* __restrict__ eWhh,
                            const float* __restrict__ ebih, const float* __restrict__ ebhh,
                            const float* __restrict__ aW,
                            const float* __restrict__ dWih, const float* __restrict__ dWhh,
                            const float* __restrict__ dbih, const float* __restrict__ dbhh,
                            const float* __restrict__ l1W, const float* __restrict__ l2W) {
    int tid = blockIdx.x * blockDim.x + threadIdx.x;
    int stride = gridDim.x * blockDim.x;
    for (int i = tid; i < ID * GD; i += stride) { int k = i / GD, j = i % GD; g_WihT_e[i] = eWih[j * ID + k]; }
    for (int i = tid; i < HD * GD; i += stride) { int k = i / GD, j = i % GD; g_WhhT_e[i] = eWhh[j * HD + k]; }
    for (int i = tid; i < GD; i += stride) g_be[i] = ebih[i] + ebhh[i];
    for (int i = tid; i < KD * GD; i += stride) { int k = i / GD, j = i % GD; g_WihT_d[i] = (k < 262) ? dWih[j * 262 + k] : 0.0f; }
    for (int i = tid; i < HD * GD; i += stride) { int k = i / GD, j = i % GD; g_WhhT_d[i] = dWhh[j * HD + k]; }
    for (int i = tid; i < GD; i += stride) g_bd[i] = dbih[i] + dbhh[i];
    for (int i = tid; i < HD * HD; i += stride) { int k = i / HD, u = i % HD; g_l1T[i] = l1W[u * HD + k]; }
    for (int i = tid; i < HD * OD; i += stride) { int k = i / OD, o = i % OD; g_l2T[i] = l2W[o * HD + k]; }
    for (int i = tid; i < LEN * KD; i += stride) { int l = i / KD, k = i % KD; g_attnW[i] = (k < 262) ? aW[l * 262 + k] : 0.0f; }
}

// ---------------- main: one CTA owns 16 batch rows end-to-end ----------------
__global__ void __launch_bounds__(NTH, 1) seq_kernel(const float* __restrict__ x,
                                                     const float* __restrict__ attn_b,
                                                     const float* __restrict__ l1b,
                                                     const float* __restrict__ l2b,
                                                     float* __restrict__ out) {
    extern __shared__ float sm[];
    float* h_s   = sm;                    // ROWS*HD
    float* c_s   = h_s + ROWS * HD;       // ROWS*HD
    float* g_s   = c_s + ROWS * HD;       // ROWS*GD (gates; reused for l1 output z)
    float* inp_s = g_s + ROWS * GD;       // ROWS*KD  ([tok(6) | ctx(256) | pad(2)])
    float* s_s   = inp_s + ROWS * KD;     // ROWS*64  (attn scores -> weights)
    float* x_s   = s_s + ROWS * 64;       // ROWS*8

    const int t  = threadIdx.x;
    const int r0 = blockIdx.x * ROWS;
    const int rg = t >> 6;                // 4 row-groups of 4 rows
    const int j0 = (t & 63) << 4;         // 16 contiguous gate columns per thread

    for (int i = t; i < ROWS * HD; i += NTH) { h_s[i] = 0.0f; c_s[i] = 0.0f; }
    __syncthreads();

    // ================= encoder =================
    for (int step = 0; step < LEN; step++) {
        if (t < ROWS * ID) {
            int r = t / ID, k = t - r * ID;
            x_s[r * 8 + k] = x[(size_t)(r0 + r) * (LEN * ID) + step * ID + k];
        }
        __syncthreads();

        u64 acc[4][8];
        {
            const ulonglong2* bp = (const ulonglong2*)&g_be[j0];
            ulonglong2 b0 = bp[0], b1 = bp[1], b2 = bp[2], b3 = bp[3];
#pragma unroll
            for (int i = 0; i < 4; i++) {
                acc[i][0] = b0.x; acc[i][1] = b0.y; acc[i][2] = b1.x; acc[i][3] = b1.y;
                acc[i][4] = b2.x; acc[i][5] = b2.y; acc[i][6] = b3.x; acc[i][7] = b3.y;
            }
        }
        // x @ WihT (K=6)
#pragma unroll
        for (int k = 0; k < ID; k++) {
            const ulonglong2* wp = (const ulonglong2*)&g_WihT_e[k * GD + j0];
            ulonglong2 w0 = wp[0], w1 = wp[1], w2 = wp[2], w3 = wp[3];
#pragma unroll
            for (int i = 0; i < 4; i++) {
                u64 ab = pack2(x_s[(rg * 4 + i) * 8 + k]);
                acc[i][0] = fma2(ab, w0.x, acc[i][0]); acc[i][1] = fma2(ab, w0.y, acc[i][1]);
                acc[i][2] = fma2(ab, w1.x, acc[i][2]); acc[i][3] = fma2(ab, w1.y, acc[i][3]);
                acc[i][4] = fma2(ab, w2.x, acc[i][4]); acc[i][5] = fma2(ab, w2.y, acc[i][5]);
                acc[i][6] = fma2(ab, w3.x, acc[i][6]); acc[i][7] = fma2(ab, w3.y, acc[i][7]);
            }
        }
        // h @ WhhT (K=256)
        gemm_part(acc, h_s, HD, HD, g_WhhT_e, rg, j0);
#pragma unroll
        for (int i = 0; i < 4; i++) {
            ulonglong2* gp = (ulonglong2*)&g_s[(rg * 4 + i) * GD + j0];
            ulonglong2 s0; s0.x = acc[i][0]; s0.y = acc[i][1]; gp[0] = s0;
            ulonglong2 s1; s1.x = acc[i][2]; s1.y = acc[i][3]; gp[1] = s1;
            ulonglong2 s2; s2.x = acc[i][4]; s2.y = acc[i][5]; gp[2] = s2;
            ulonglong2 s3; s3.x = acc[i][6]; s3.y = acc[i][7]; gp[3] = s3;
        }
        __syncthreads();

        // cell update + write enc_out (u interleaved: conflict-free LDS + coalesced STG)
        {
            int r = t >> 4, ul = t & 15;
            float* gr = &g_s[r * GD];
            float* hr = &h_s[r * HD];
            float* cr = &c_s[r * HD];
            float* er = &g_enc[(size_t)(r0 + r) * (LEN * HD) + step * HD];
#pragma unroll
            for (int z = 0; z < 16; z++) {
                int u = ul + z * 16;
                float gi = gr[u], gf = gr[HD + u], gg = gr[2 * HD + u], go = gr[3 * HD + u];
                float cc = sigmf(gf) * cr[u] + sigmf(gi) * tanhf(gg);
                float hh = sigmf(go) * tanhf(cc);
                cr[u] = cc; hr[u] = hh; er[u] = hh;
            }
        }
        __syncthreads();
    }

    // ================= decoder init: c=0, tok=GO =================
    for (int i = t; i < ROWS * HD; i += NTH) c_s[i] = 0.0f;
    if (t < ROWS) {
#pragma unroll
        for (int k = 0; k < OD; k++) inp_s[t * KD + k] = (k == 4) ? 1.0f : 0.0f;
        inp_s[t * KD + 262] = 0.0f; inp_s[t * KD + 263] = 0.0f;
    }
    __syncthreads();

    // ================= decoder =================
    for (int step = 0; step < TS; step++) {
        // attention scores: s[r][l] = [h, tok] . attn_W[l] + b[l]
        for (int idx = t; idx < ROWS * LEN; idx += NTH) {
            int r = idx / LEN, l = idx - r * LEN;
            const float* wr = &g_attnW[l * KD];
            const float4* wp4 = (const float4*)wr;
            const float4* hp4 = (const float4*)&h_s[r * HD];
            float4 a4 = make_float4(0.0f, 0.0f, 0.0f, 0.0f);
#pragma unroll 8
            for (int k = 0; k < HD / 4; k++) {
                float4 hv = hp4[k], wv = wp4[k];
                a4.x += hv.x * wv.x; a4.y += hv.y * wv.y;
                a4.z += hv.z * wv.z; a4.w += hv.w * wv.w;
            }
            float s = attn_b[l] + a4.x + a4.y + a4.z + a4.w;
#pragma unroll
            for (int k = 0; k < OD; k++) s += inp_s[r * KD + k] * wr[HD + k];
            s_s[r * 64 + l] = s;
        }
        __syncthreads();
        // softmax (one thread per row; tiny)
        if (t < ROWS) {
            float* sp = &s_s[t * 64];
            float m = -1e30f;
            for (int l = 0; l < LEN; l++) m = fmaxf(m, sp[l]);
            float ssum = 0.0f;
            for (int l = 0; l < LEN; l++) { float e = __expf(sp[l] - m); sp[l] = e; ssum += e; }
            float inv = 1.0f / ssum;
            for (int l = 0; l < LEN; l++) sp[l] *= inv;
        }
        __syncthreads();
        // ctx[r][h] = sum_l aw[r][l] * enc_out[r][l][h]  -> inp_s[r][6+h]
        {
            int r = t >> 4, h0 = (t & 15) * 16;
            u64 a8[8];
#pragma unroll
            for (int z = 0; z < 8; z++) a8[z] = 0ULL;
            const float* ep = &g_enc[(size_t)(r0 + r) * (LEN * HD) + h0];
            const float* ap = &s_s[r * 64];
            for (int l = 0; l < LEN; l++) {
                u64 ab = pack2(ap[l]);
                const ulonglong2* e2 = (const ulonglong2*)(ep + (size_t)l * HD);
                ulonglong2 e0 = e2[0], e1 = e2[1], e2v = e2[2], e3 = e2[3];
                a8[0] = fma2(ab, e0.x, a8[0]);  a8[1] = fma2(ab, e0.y, a8[1]);
                a8[2] = fma2(ab, e1.x, a8[2]);  a8[3] = fma2(ab, e1.y, a8[3]);
                a8[4] = fma2(ab, e2v.x, a8[4]); a8[5] = fma2(ab, e2v.y, a8[5]);
                a8[6] = fma2(ab, e3.x, a8[6]);  a8[7] = fma2(ab, e3.y, a8[7]);
            }
            float* dst = &inp_s[r * KD + OD + h0];
#pragma unroll
            for (int z = 0; z < 8; z++) { float2 f = unpk(a8[z]); dst[2 * z] = f.x; dst[2 * z + 1] = f.y; }
        }
        __syncthreads();

        // decoder LSTM gates: g = inp @ dec_WihT (K=264, zero-padded) + h @ dec_WhhT + b
        u64 acc[4][8];
        {
            const ulonglong2* bp = (const ulonglong2*)&g_bd[j0];
            ulonglong2 b0 = bp[0], b1 = bp[1], b2 = bp[2], b3 = bp[3];
#pragma unroll
            for (int i = 0; i < 4; i++) {
                acc[i][0] = b0.x; acc[i][1] = b0.y; acc[i][2] = b1.x; acc[i][3] = b1.y;
                acc[i][4] = b2.x; acc[i][5] = b2.y; acc[i][6] = b3.x; acc[i][7] = b3.y;
            }
        }
        gemm_part(acc, inp_s, KD, KD, g_WihT_d, rg, j0);
        gemm_part(acc, h_s, HD, HD, g_WhhT_d, rg, j0);
#pragma unroll
        for (int i = 0; i < 4; i++) {
            ulonglong2* gp = (ulonglong2*)&g_s[(rg * 4 + i) * GD + j0];
            ulonglong2 s0; s0.x = acc[i][0]; s0.y = acc[i][1]; gp[0] = s0;
            ulonglong2 s1; s1.x = acc[i][2]; s1.y = acc[i][3]; gp[1] = s1;
            ulonglong2 s2; s2.x = acc[i][4]; s2.y = acc[i][5]; gp[2] = s2;
            ulonglong2 s3; s3.x = acc[i][6]; s3.y = acc[i][7]; gp[3] = s3;
        }
        __syncthreads();

        // cell update
        {
            int r = t >> 4, ul = t & 15;
            float* gr = &g_s[r * GD];
            float* hr = &h_s[r * HD];
            float* cr = &c_s[r * HD];
#pragma unroll
            for (int z = 0; z < 16; z++) {
                int u = ul + z * 16;
                float gi = gr[u], gf = gr[HD + u], gg = gr[2 * HD + u], go = gr[3 * HD + u];
                float cc = sigmf(gf) * cr[u] + sigmf(gi) * tanhf(gg);
                float hh = sigmf(go) * tanhf(cc);
                cr[u] = cc; hr[u] = hh;
            }
        }
        __syncthreads();

        // l1: z = relu(h @ l1T + b1)  -> store into g_s[r][u] (u < 256)
        {
            int u0 = (t & 63) * 4;
            u64 az[4][2];
            ulonglong2 lb = *(const ulonglong2*)&l1b[u0];
#pragma unroll
            for (int i = 0; i < 4; i++) { az[i][0] = lb.x; az[i][1] = lb.y; }
            for (int k = 0; k < HD; k += 4) {
                float4 hv[4];
#pragma unroll
                for (int i = 0; i < 4; i++) hv[i] = *(const float4*)&h_s[(rg * 4 + i) * HD + k];
#pragma unroll
                for (int kk = 0; kk < 4; kk++) {
                    ulonglong2 w = *(const ulonglong2*)&g_l1T[(k + kk) * HD + u0];
#pragma unroll
                    for (int i = 0; i < 4; i++) {
                        u64 ab = pack2(((const float*)&hv[i])[kk]);
                        az[i][0] = fma2(ab, w.x, az[i][0]);
                        az[i][1] = fma2(ab, w.y, az[i][1]);
                    }
                }
            }
#pragma unroll
            for (int i = 0; i < 4; i++) {
                float2 f0 = unpk(az[i][0]), f1 = unpk(az[i][1]);
                float* zr = &g_s[(rg * 4 + i) * GD + u0];
                zr[0] = fmaxf(f0.x, 0.0f); zr[1] = fmaxf(f0.y, 0.0f);
                zr[2] = fmaxf(f1.x, 0.0f); zr[3] = fmaxf(f1.y, 0.0f);
            }
        }
        __syncthreads();

        // l2 + output + token feedback
        if (t < ROWS * OD) {
            int r = t / OD, o = t - r * OD;
            float s = l2b[o];
            const float* zr = &g_s[r * GD];
            for (int k = 0; k < HD; k++) s += zr[k] * g_l2T[k * OD + o];
            out[(size_t)(r0 + r) * (TS * OD) + step * OD + o] = s;
            inp_s[r * KD + o] = s;
        }
        __syncthreads();
    }
}

extern "C" void kernel_launch(void* const* d_in, const int* in_sizes, int n_in,
                              void* d_out, int out_size) {
    const float* x    = (const float*)d_in[0];
    // d_in[1] = target (unused; only its length T=60 matters, which is compile-time)
    const float* eWih = (const float*)d_in[2];
    const float* eWhh = (const float*)d_in[3];
    const float* ebih = (const float*)d_in[4];
    const float* ebhh = (const float*)d_in[5];
    const float* aW   = (const float*)d_in[6];
    const float* ab   = (const float*)d_in[7];
    const float* dWih = (const float*)d_in[8];
    const float* dWhh = (const float*)d_in[9];
    const float* dbih = (const float*)d_in[10];
    const float* dbhh = (const float*)d_in[11];
    const float* l1W  = (const float*)d_in[12];
    const float* l1b  = (const float*)d_in[13];
    const float* l2W  = (const float*)d_in[14];
    const float* l2b  = (const float*)d_in[15];
    float* out = (float*)d_out;

    prep_kernel<<<256, 256>>>(eWih, eWhh, ebih, ebhh, aW, dWih, dWhh, dbih, dbhh, l1W, l2W);

    const int smem_bytes = (ROWS * HD * 2 + ROWS * GD + ROWS * KD + ROWS * 64 + ROWS * 8) * (int)sizeof(float);
    cudaFuncSetAttribute(seq_kernel, cudaFuncAttributeMaxDynamicSharedMemorySize, smem_bytes);
    seq_kernel<<<NCTA, NTH, smem_bytes>>>(x, ab, l1b, l2b, out);
}